// round 8
// baseline (speedup 1.0000x reference)
#include <cuda_runtime.h>

#define NGRID 48
#define N3 (NGRID * NGRID * NGRID)
#define NATOMS_MAX 1024
#define TILE 4
#define TILES_X (NGRID / TILE)        // 12
#define NBLOCKS (TILES_X * TILES_X)   // 144
#define NTHREADS 1024

// r^2 exactly as the reference: float32((1.5*1.52)**2), product in double.
__device__ __forceinline__ float ref_r2() {
    const double r = 1.5 * 1.52;
    return (float)(r * r);
}

// Exact reference-rounded test: RN(sxy + RN(dz*dz)) < R2, dz = RN(az - 0.5*z).
__device__ __forceinline__ bool exact_pass(float sxy, float az, int z, float R2) {
    const float dz = __fsub_rn(az, 0.5f * (float)z);
    return __fadd_rn(sxy, __fmul_rn(dz, dz)) < R2;
}

__global__ __launch_bounds__(NTHREADS)
void wat_mask_kernel(const float* __restrict__ vecs, int n_atoms,
                     float* __restrict__ out) {
    __shared__ float4 satom[NATOMS_MAX];  // compacted culled atoms
    __shared__ int scnt[32];              // per-warp match counts

    const float R2 = ref_r2();            // ~5.1984
    const float RM = 2.2802f;             // > sqrt(R2): conservative margin

    const int bx = blockIdx.x % TILES_X;
    const int by = blockIdx.x / TILES_X;
    const int x0 = bx * TILE;
    const int y0 = by * TILE;

    const int tid  = threadIdx.x;
    const int wid  = tid >> 5;            // 32 warps
    const int lane = tid & 31;

    // ---- Phase 1: one atom per thread, cull vs expanded tile AABB.
    const bool v0 = (tid < n_atoms);
    float ax = 0.f, ay = 0.f, az = 0.f;
    if (v0) { ax = vecs[3*tid]; ay = vecs[3*tid+1]; az = vecs[3*tid+2]; }

    const float xmin = 0.5f * (float)x0 - RM;
    const float xmax = 0.5f * (float)(x0 + TILE - 1) + RM;
    const float ymin = 0.5f * (float)y0 - RM;
    const float ymax = 0.5f * (float)(y0 + TILE - 1) + RM;

    const bool match = v0 && ax >= xmin && ax <= xmax
                          && ay >= ymin && ay <= ymax;
    const unsigned m = __ballot_sync(0xffffffffu, match);
    if (lane == 0) scnt[wid] = __popc(m);
    __syncthreads();

    // ---- Offsets via REDUX: base_w = sum of counts of warps < wid.
    const int c_l   = scnt[lane];
    const int base  = __reduce_add_sync(0xffffffffu, (lane < wid) ? c_l : 0);
    const int total = __reduce_add_sync(0xffffffffu, c_l);

    if (match) {
        const int p = base + __popc(m & ((1u << lane) - 1u));
        satom[p] = make_float4(ax, ay, az, 0.f);
    }
    __syncthreads();

    // Warps 16-31 are done (they participated in both barriers).
    if (wid >= TILE * TILE) return;

    // ---- Phase 2: one warp per column. Passing z-set per atom is a
    // contiguous interval (RN-monotone). sqrt gives the boundary index to
    // within +/-1 (total estimate error < 0.01 index, incl. the RN-threshold
    // shift and degenerate small radii), so each end is resolved by TWO
    // exact reference-rounded tests, branchlessly (no walk loops).
    const int cx = wid >> 2;
    const int cy = wid & 3;
    const float px = 0.5f * (float)(x0 + cx);         // exact in fp32
    const float py = 0.5f * (float)(y0 + cy);

    unsigned long long mask = 0ull;
    for (int j = lane; j < total; j += 32) {
        const float4 a = satom[j];
        const float dx  = __fsub_rn(a.x, px);
        const float dy  = __fsub_rn(a.y, py);
        const float sxy = __fadd_rn(__fmul_rn(dx, dx), __fmul_rn(dy, dy));
        if (sxy < R2) {                   // rigorous: else RN(sxy+dz^2)>=sxy
            const float azj = a.z;
            const float rad = sqrtf(__fsub_rn(R2, sxy));
            const float ul  = __fsub_rn(azj, rad);
            const float uh  = __fadd_rn(azj, rad);
            const int e = (int)ceilf(__fadd_rn(ul, ul));    // 2*(az-rad)
            const int f = (int)floorf(__fadd_rn(uh, uh));   // 2*(az+rad)

            // Low end: true zl in {e-1, e, e+1}; high end mirrored.
            const bool pl0 = exact_pass(sxy, azj, e - 1, R2);
            const bool pl1 = exact_pass(sxy, azj, e,     R2);
            const bool ph0 = exact_pass(sxy, azj, f + 1, R2);
            const bool ph1 = exact_pass(sxy, azj, f,     R2);
            int zl = pl0 ? e - 1 : (pl1 ? e : e + 1);
            int zh = ph0 ? f + 1 : (ph1 ? f : f - 1);
            zl = max(zl, 0);
            zh = min(zh, NGRID - 1);
            const int len = zh - zl + 1;                    // <= 48
            if (len > 0)
                mask |= ((1ull << len) - 1ull) << zl;
        }
    }
    const unsigned lo = __reduce_or_sync(0xffffffffu, (unsigned)mask);
    const unsigned hi = __reduce_or_sync(0xffffffffu, (unsigned)(mask >> 32));
    mask = (unsigned long long)lo | ((unsigned long long)hi << 32);

    // ---- Epilogue: warp-direct stores, no barrier. Lanes 0-11 write ch0,
    // lanes 12-23 write ch1 (12 float4 each = 192B contiguous per channel).
    if (lane < 24) {
        const int ch = (lane >= 12);
        const int zq = ch ? lane - 12 : lane;
        const unsigned bits = (unsigned)(mask >> (4 * zq)) & 0xFu;

        const float on  = ch ? 25.0f : 1.0f;
        const float off = ch ? 1.0f  : 0.0f;
        float4 v;
        v.x = (bits & 1u) ? on : off;
        v.y = (bits & 2u) ? on : off;
        v.z = (bits & 4u) ? on : off;
        v.w = (bits & 8u) ? on : off;

        const int gx = x0 + cx;
        const int gy = y0 + cy;
        const int idx = ch * N3 + (gx * NGRID + gy) * NGRID + 4 * zq;
        *reinterpret_cast<float4*>(out + idx) = v;
    }
}

extern "C" void kernel_launch(void* const* d_in, const int* in_sizes, int n_in,
                              void* d_out, int out_size) {
    const float* vecs = (const float*)d_in[0];
    const int n_atoms = in_sizes[0] / 3;
    float* out = (float*)d_out;
    wat_mask_kernel<<<NBLOCKS, NTHREADS>>>(vecs, n_atoms, out);
}

// round 9
// speedup vs baseline: 1.0046x; 1.0046x over previous
#include <cuda_runtime.h>

#define NGRID 48
#define N3 (NGRID * NGRID * NGRID)
#define NATOMS_MAX 1024
#define TILE 4
#define TILES_X (NGRID / TILE)        // 12
#define NBLOCKS (TILES_X * TILES_X)   // 144
#define NTHREADS 1024

// r^2 exactly as the reference: float32((1.5*1.52)**2), product in double.
__device__ __forceinline__ float ref_r2() {
    const double r = 1.5 * 1.52;
    return (float)(r * r);
}

// Exact reference-rounded test with precomputed voxel coord zf = 0.5*z
// (half-integers are exact in fp32): RN(sxy + RN(dz*dz)) < R2.
__device__ __forceinline__ bool exact_pass_f(float sxy, float az, float zf, float R2) {
    const float dz = __fsub_rn(az, zf);
    return __fadd_rn(sxy, __fmul_rn(dz, dz)) < R2;
}

__global__ __launch_bounds__(NTHREADS)
void wat_mask_kernel(const float* __restrict__ vecs, int n_atoms,
                     float* __restrict__ out) {
    __shared__ float4 satom[NATOMS_MAX];  // compacted culled atoms
    __shared__ int scnt[32];              // per-warp match counts

    const float R2 = ref_r2();            // ~5.1984
    const float RM = 2.2802f;             // > sqrt(R2): conservative margin

    const int bx = blockIdx.x % TILES_X;
    const int by = blockIdx.x / TILES_X;
    const int x0 = bx * TILE;
    const int y0 = by * TILE;

    const int tid  = threadIdx.x;
    const int wid  = tid >> 5;            // 32 warps
    const int lane = tid & 31;

    // ---- Phase 1: one atom per thread, cull vs expanded tile AABB.
    const bool v0 = (tid < n_atoms);
    float ax = 0.f, ay = 0.f, az = 0.f;
    if (v0) { ax = vecs[3*tid]; ay = vecs[3*tid+1]; az = vecs[3*tid+2]; }

    const float xmin = 0.5f * (float)x0 - RM;
    const float xmax = 0.5f * (float)(x0 + TILE - 1) + RM;
    const float ymin = 0.5f * (float)y0 - RM;
    const float ymax = 0.5f * (float)(y0 + TILE - 1) + RM;

    const bool match = v0 && ax >= xmin && ax <= xmax
                          && ay >= ymin && ay <= ymax;
    const unsigned m = __ballot_sync(0xffffffffu, match);
    if (lane == 0) scnt[wid] = __popc(m);
    __syncthreads();

    // ---- Offsets via REDUX: base_w = sum of counts of warps < wid.
    const int c_l   = scnt[lane];
    const int base  = __reduce_add_sync(0xffffffffu, (lane < wid) ? c_l : 0);
    const int total = __reduce_add_sync(0xffffffffu, c_l);

    if (match) {
        const int p = base + __popc(m & ((1u << lane) - 1u));
        satom[p] = make_float4(ax, ay, az, 0.f);
    }
    __syncthreads();

    // Warps 16-31 are done (they participated in both barriers).
    if (wid >= TILE * TILE) return;

    // ---- Phase 2: one warp per column. Passing z-set per atom is a
    // contiguous interval (RN-monotone). Approximate sqrt (x*rsqrt(x),
    // <=2ulp; x>0 strictly) locates each boundary to within +/-1 index;
    // each end is then resolved by TWO exact reference-rounded tests,
    // branchlessly. Every set bit is certified by the exact test.
    const int cx = wid >> 2;
    const int cy = wid & 3;
    const float px = 0.5f * (float)(x0 + cx);         // exact in fp32
    const float py = 0.5f * (float)(y0 + cy);

    unsigned long long mask = 0ull;
    for (int j = lane; j < total; j += 32) {
        const float4 a = satom[j];
        const float dx  = __fsub_rn(a.x, px);
        const float dy  = __fsub_rn(a.y, py);
        const float sxy = __fadd_rn(__fmul_rn(dx, dx), __fmul_rn(dy, dy));
        if (sxy < R2) {                   // rigorous: else RN(sxy+dz^2)>=sxy
            const float azj = a.z;
            const float x   = __fsub_rn(R2, sxy);     // > 0 strictly
            const float rad = __fmul_rn(x, __frsqrt_rn(x));  // ~sqrt(x)
            const float ul  = __fsub_rn(azj, rad);
            const float uh  = __fadd_rn(azj, rad);
            const int e = __float2int_ru(__fadd_rn(ul, ul)); // ceil(2*(az-rad))
            const int f = __float2int_rd(__fadd_rn(uh, uh)); // floor(2*(az+rad))

            const float ze = 0.5f * (float)e;         // exact half-integers
            const float zf = 0.5f * (float)f;

            // Low end: true zl in {e-1, e, e+1}; high end mirrored.
            const bool pl0 = exact_pass_f(sxy, azj, ze - 0.5f, R2);
            const bool pl1 = exact_pass_f(sxy, azj, ze,        R2);
            const bool ph0 = exact_pass_f(sxy, azj, zf + 0.5f, R2);
            const bool ph1 = exact_pass_f(sxy, azj, zf,        R2);
            int zl = pl0 ? e - 1 : (pl1 ? e : e + 1);
            int zh = ph0 ? f + 1 : (ph1 ? f : f - 1);
            zl = max(zl, 0);
            zh = min(zh, NGRID - 1);
            const int len = zh - zl + 1;              // <= 48
            if (len > 0)
                mask |= ((1ull << len) - 1ull) << zl;
        }
    }
    const unsigned lo = __reduce_or_sync(0xffffffffu, (unsigned)mask);
    const unsigned hi = __reduce_or_sync(0xffffffffu, (unsigned)(mask >> 32));
    mask = (unsigned long long)lo | ((unsigned long long)hi << 32);

    // ---- Epilogue: warp-direct stores, no barrier. Lanes 0-11 write ch0,
    // lanes 12-23 write ch1 (12 float4 each = 192B contiguous per channel).
    if (lane < 24) {
        const int ch = (lane >= 12);
        const int zq = ch ? lane - 12 : lane;
        const unsigned bits = (unsigned)(mask >> (4 * zq)) & 0xFu;

        const float on  = ch ? 25.0f : 1.0f;
        const float off = ch ? 1.0f  : 0.0f;
        float4 v;
        v.x = (bits & 1u) ? on : off;
        v.y = (bits & 2u) ? on : off;
        v.z = (bits & 4u) ? on : off;
        v.w = (bits & 8u) ? on : off;

        const int gx = x0 + cx;
        const int gy = y0 + cy;
        const int idx = ch * N3 + (gx * NGRID + gy) * NGRID + 4 * zq;
        *reinterpret_cast<float4*>(out + idx) = v;
    }
}

extern "C" void kernel_launch(void* const* d_in, const int* in_sizes, int n_in,
                              void* d_out, int out_size) {
    const float* vecs = (const float*)d_in[0];
    const int n_atoms = in_sizes[0] / 3;
    float* out = (float*)d_out;
    wat_mask_kernel<<<NBLOCKS, NTHREADS>>>(vecs, n_atoms, out);
}

// round 10
// speedup vs baseline: 1.0483x; 1.0435x over previous
#include <cuda_runtime.h>

#define NGRID 48
#define N3 (NGRID * NGRID * NGRID)
#define NATOMS_MAX 1024
#define TILE 4
#define TILES_X (NGRID / TILE)        // 12
#define NBLOCKS (TILES_X * TILES_X)   // 144
#define NTHREADS 1024

// r^2 exactly as the reference: float32((1.5*1.52)**2), product in double.
__device__ __forceinline__ float ref_r2() {
    const double r = 1.5 * 1.52;
    return (float)(r * r);
}

// Exact reference-rounded test with precomputed voxel coord zf = 0.5*z
// (half-integers are exact in fp32): RN(sxy + RN(dz*dz)) < R2.
__device__ __forceinline__ bool exact_pass_f(float sxy, float az, float zf, float R2) {
    const float dz = __fsub_rn(az, zf);
    return __fadd_rn(sxy, __fmul_rn(dz, dz)) < R2;
}

__global__ __launch_bounds__(NTHREADS)
void wat_mask_kernel(const float* __restrict__ vecs, int n_atoms,
                     float* __restrict__ out) {
    __shared__ float4 satom[NATOMS_MAX];  // compacted culled atoms
    __shared__ int scnt[32];              // per-warp match counts

    const float R2 = ref_r2();            // ~5.1984
    const float RM = 2.2802f;             // > sqrt(R2): conservative margin

    const int bx = blockIdx.x % TILES_X;
    const int by = blockIdx.x / TILES_X;
    const int x0 = bx * TILE;
    const int y0 = by * TILE;

    const int tid  = threadIdx.x;
    const int wid  = tid >> 5;            // 32 warps
    const int lane = tid & 31;

    // ---- Phase 1: one atom per thread, cull vs expanded tile AABB.
    const bool v0 = (tid < n_atoms);
    float ax = 0.f, ay = 0.f, az = 0.f;
    if (v0) { ax = vecs[3*tid]; ay = vecs[3*tid+1]; az = vecs[3*tid+2]; }

    const float xmin = 0.5f * (float)x0 - RM;
    const float xmax = 0.5f * (float)(x0 + TILE - 1) + RM;
    const float ymin = 0.5f * (float)y0 - RM;
    const float ymax = 0.5f * (float)(y0 + TILE - 1) + RM;

    const bool match = v0 && ax >= xmin && ax <= xmax
                          && ay >= ymin && ay <= ymax;
    const unsigned m = __ballot_sync(0xffffffffu, match);
    if (lane == 0) scnt[wid] = __popc(m);
    __syncthreads();

    // ---- Offsets via REDUX: base_w = sum of counts of warps < wid.
    const int c_l   = scnt[lane];
    const int base  = __reduce_add_sync(0xffffffffu, (lane < wid) ? c_l : 0);
    const int total = __reduce_add_sync(0xffffffffu, c_l);

    if (match) {
        const int p = base + __popc(m & ((1u << lane) - 1u));
        satom[p] = make_float4(ax, ay, az, 0.f);
    }
    __syncthreads();

    // Warps 16-31 are done (they participated in both barriers).
    if (wid >= TILE * TILE) return;

    // ---- Phase 2: one warp per column. Passing z-set per atom is a
    // contiguous interval (RN-monotone). sqrt.rn locates each boundary
    // index to within +/-1; each end is resolved by TWO exact
    // reference-rounded tests, branchlessly (no walk loops). Every set
    // bit is certified by the exact test or monotone interpolation.
    const int cx = wid >> 2;
    const int cy = wid & 3;
    const float px = 0.5f * (float)(x0 + cx);         // exact in fp32
    const float py = 0.5f * (float)(y0 + cy);

    unsigned long long mask = 0ull;
    for (int j = lane; j < total; j += 32) {
        const float4 a = satom[j];
        const float dx  = __fsub_rn(a.x, px);
        const float dy  = __fsub_rn(a.y, py);
        const float sxy = __fadd_rn(__fmul_rn(dx, dx), __fmul_rn(dy, dy));
        if (sxy < R2) {                   // rigorous: else RN(sxy+dz^2)>=sxy
            const float azj = a.z;
            const float rad = sqrtf(__fsub_rn(R2, sxy));
            const float az2 = __fadd_rn(azj, azj);    // 2*az (exact)
            const float r2x = __fadd_rn(rad, rad);    // 2*rad
            const int e = __float2int_ru(__fsub_rn(az2, r2x)); // ceil(2(az-rad))
            const int f = __float2int_rd(__fadd_rn(az2, r2x)); // floor(2(az+rad))

            const float ze = 0.5f * (float)e;         // exact half-integers
            const float zf = 0.5f * (float)f;

            // Low end: true zl in {e-1, e, e+1}; high end mirrored.
            const bool pl0 = exact_pass_f(sxy, azj, ze - 0.5f, R2);
            const bool pl1 = exact_pass_f(sxy, azj, ze,        R2);
            const bool ph0 = exact_pass_f(sxy, azj, zf + 0.5f, R2);
            const bool ph1 = exact_pass_f(sxy, azj, zf,        R2);
            int zl = pl0 ? e - 1 : (pl1 ? e : e + 1);
            int zh = ph0 ? f + 1 : (ph1 ? f : f - 1);
            zl = max(zl, 0);
            zh = min(zh, NGRID - 1);
            const int len = zh - zl + 1;              // <= 48
            if (len > 0)
                mask |= ((1ull << len) - 1ull) << zl;
        }
    }
    const unsigned lo = __reduce_or_sync(0xffffffffu, (unsigned)mask);
    const unsigned hi = __reduce_or_sync(0xffffffffu, (unsigned)(mask >> 32));
    mask = (unsigned long long)lo | ((unsigned long long)hi << 32);

    // ---- Epilogue: warp-direct stores, no barrier. Lanes 0-11 write ch0,
    // lanes 12-23 write ch1 (12 float4 each = 192B contiguous per channel).
    if (lane < 24) {
        const int ch = (lane >= 12);
        const int zq = ch ? lane - 12 : lane;
        const unsigned bits = (unsigned)(mask >> (4 * zq)) & 0xFu;

        const float on  = ch ? 25.0f : 1.0f;
        const float off = ch ? 1.0f  : 0.0f;
        float4 v;
        v.x = (bits & 1u) ? on : off;
        v.y = (bits & 2u) ? on : off;
        v.z = (bits & 4u) ? on : off;
        v.w = (bits & 8u) ? on : off;

        const int gx = x0 + cx;
        const int gy = y0 + cy;
        const int idx = ch * N3 + (gx * NGRID + gy) * NGRID + 4 * zq;
        *reinterpret_cast<float4*>(out + idx) = v;
    }
}

extern "C" void kernel_launch(void* const* d_in, const int* in_sizes, int n_in,
                              void* d_out, int out_size) {
    const float* vecs = (const float*)d_in[0];
    const int n_atoms = in_sizes[0] / 3;
    float* out = (float*)d_out;
    wat_mask_kernel<<<NBLOCKS, NTHREADS>>>(vecs, n_atoms, out);
}